// round 7
// baseline (speedup 1.0000x reference)
#include <cuda_runtime.h>

#define Bb 2
#define Ll 2048
#define Dd 128
#define Hh 8
#define HDd 32
#define HB (Hh*Bb)   // 16
#define SCALE 0.17677669529663687f
#define QT 64

// ---------------- device scratch (no allocs allowed) ----------------
__device__ float4 Qd4[HB * Ll * 8];        // [h*B+b][l][d] as float4 x8, 4MB
__device__ float4 Kd4[HB * Ll * 8];        // 4MB
__device__ float  Vg[HB * Ll];             // sigmoid(x@Wv), [h*B+b][l]
__device__ float  denomP[2][HB * Ll];      // softmax denominators, 2-way key split
__device__ float  Spart[2][HB * Ll];       // distance histogram, 2-way q split

// ---------------- stage 1: projections ----------------
// 256 blocks x 256 threads; each block handles 16 (b,l) rows, thread t = output col.
__global__ void proj_kernel(const float* __restrict__ x, const float* __restrict__ pe,
                            const float* __restrict__ Wq, const float* __restrict__ bq,
                            const float* __restrict__ Wk, const float* __restrict__ bk,
                            const float* __restrict__ Wv) {
    const int ROWS = 16;
    __shared__ float xs[ROWS][Dd];   // raw x (for v)
    __shared__ float xps[ROWS][Dd];  // x + pe (for q,k)
    int t = threadIdx.x;             // 0..255
    int row0 = blockIdx.x * ROWS;    // global row = b*L + l (16 rows share b: L%16==0)
    int b = row0 / Ll;
    int l0 = row0 % Ll;

    for (int i = t; i < ROWS * Dd; i += 256) {
        int r = i >> 7, dd = i & 127;
        float xv = x[(row0 + r) * Dd + dd];
        xs[r][dd]  = xv;
        xps[r][dd] = xv + pe[(l0 + r) * Dd + dd];
    }
    __syncthreads();

    float accq[ROWS], acck[ROWS], accv[ROWS];
    float bqv = bq[t], bkv = bk[t];
    #pragma unroll
    for (int r = 0; r < ROWS; r++) { accq[r] = bqv; acck[r] = bkv; accv[r] = 0.f; }

    for (int dd = 0; dd < Dd; dd++) {
        float wq = Wq[dd * 256 + t];
        float wk = Wk[dd * 256 + t];
        float wv = (t < Hh) ? Wv[dd * Hh + t] : 0.f;
        #pragma unroll
        for (int r = 0; r < ROWS; r++) {
            float xpv = xps[r][dd];
            accq[r] += xpv * wq;
            acck[r] += xpv * wk;
            accv[r] += xs[r][dd] * wv;  // only meaningful for t < 8
        }
    }

    int h = t >> 5, d = t & 31;
    float* Qs = (float*)Qd4;
    float* Ks = (float*)Kd4;
    #pragma unroll
    for (int r = 0; r < ROWS; r++) {
        int l = l0 + r;
        Qs[((h * Bb + b) * Ll + l) * 32 + d] = accq[r];
        Ks[((h * Bb + b) * Ll + l) * 32 + d] = acck[r];
        if (t < Hh)
            Vg[(t * Bb + b) * Ll + l] = 1.f / (1.f + __expf(-accv[r]));
    }
}

// ---------------- stage 2: softmax denominators ----------------
// 512 blocks x 128 threads. block = (hb, qchunk of 128, ks half of key tiles)
__global__ void denom_kernel() {
    __shared__ float4 ks4[128][8];
    int t = threadIdx.x;
    int bx = blockIdx.x;
    int hb = bx >> 5;
    int rem = bx & 31;
    int qc = rem >> 1;
    int ks = rem & 1;
    int q = qc * 128 + t;

    float4 qv[8];
    #pragma unroll
    for (int d4 = 0; d4 < 8; d4++) qv[d4] = Qd4[(hb * Ll + q) * 8 + d4];

    float acc = 0.f;
    for (int kt = ks; kt < 16; kt += 2) {
        #pragma unroll
        for (int d4 = 0; d4 < 8; d4++)
            ks4[t][d4] = Kd4[(hb * Ll + kt * 128 + t) * 8 + d4];
        __syncthreads();
        #pragma unroll 4
        for (int j = 0; j < 128; j++) {
            float s0 = 0.f, s1 = 0.f, s2 = 0.f, s3 = 0.f;
            #pragma unroll
            for (int d4 = 0; d4 < 8; d4++) {
                float4 kk = ks4[j][d4];
                float4 qq = qv[d4];
                s0 += qq.x * kk.x; s1 += qq.y * kk.y;
                s2 += qq.z * kk.z; s3 += qq.w * kk.w;
            }
            acc += __expf(((s0 + s1) + (s2 + s3)) * SCALE);
        }
        __syncthreads();
    }
    denomP[ks][hb * Ll + q] = acc;
}

// ---------------- stage 3: diagonal accumulation ----------------
// 512 blocks x 128 threads. block = (hb, mchunk of 128, qs half of q tiles).
// thread owns distance m = mchunk*128 + t; accumulates S[m] in a register.
__global__ void attn_kernel() {
    __shared__ float4 qs4[QT][8];      // q tile, broadcast reads
    __shared__ float  kT[32][193];     // k tile transposed, padded: conflict-free
    __shared__ float  dinv[QT];        // 1/denom per query
    __shared__ float  vvs[192];        // v gate per key row
    int t = threadIdx.x;
    int bx = blockIdx.x;
    int hb = bx >> 5;
    int rem = bx & 31;
    int mc = rem >> 1;
    int qs = rem & 1;
    int m0 = mc * 128;
    int m = m0 + t;

    float acc = 0.f;
    for (int q0 = qs * QT; q0 < Ll - m0; q0 += 2 * QT) {
        int kbase = q0 + m0;
        // q tile: 64 rows x 8 float4
        for (int i = t; i < QT * 8; i += 128) {
            int ri = i >> 3, d4 = i & 7;
            int row = q0 + ri;
            qs4[ri][d4] = (row < Ll) ? Qd4[(hb * Ll + row) * 8 + d4]
                                     : make_float4(0.f, 0.f, 0.f, 0.f);
        }
        // k tile transposed: 192 rows x 32 dims -> kT[d][row]
        for (int i = t; i < 192 * 8; i += 128) {
            int ri = i >> 3, d4 = i & 7;
            int row = kbase + ri;
            float4 kv = (row < Ll) ? Kd4[(hb * Ll + row) * 8 + d4]
                                   : make_float4(0.f, 0.f, 0.f, 0.f);
            kT[d4 * 4 + 0][ri] = kv.x;
            kT[d4 * 4 + 1][ri] = kv.y;
            kT[d4 * 4 + 2][ri] = kv.z;
            kT[d4 * 4 + 3][ri] = kv.w;
        }
        if (t < QT) {
            int row = q0 + t;
            dinv[t] = (row < Ll)
                ? __fdividef(1.f, denomP[0][hb * Ll + row] + denomP[1][hb * Ll + row])
                : 0.f;
        }
        for (int i = t; i < 192; i += 128) {
            int kk = kbase + i;
            vvs[i] = (kk < Ll) ? Vg[hb * Ll + (Ll - 1 - kk)] : 0.f;
        }
        __syncthreads();

        int n = Ll - m - q0;             // valid iff q0+qi+m < L
        if (n > QT) n = QT;
        for (int qi = 0; qi < n; qi++) {
            int r = qi + t;              // <= 63+127 = 190 < 192
            float s0 = 0.f, s1 = 0.f, s2 = 0.f, s3 = 0.f;
            #pragma unroll
            for (int d4 = 0; d4 < 8; d4++) {
                float4 qq = qs4[qi][d4];
                s0 += qq.x * kT[d4 * 4 + 0][r];
                s1 += qq.y * kT[d4 * 4 + 1][r];
                s2 += qq.z * kT[d4 * 4 + 2][r];
                s3 += qq.w * kT[d4 * 4 + 3][r];
            }
            acc += __expf(((s0 + s1) + (s2 + s3)) * SCALE) * dinv[qi] * vvs[r];
        }
        __syncthreads();
    }
    Spart[qs][hb * Ll + m] = acc;
}

// ---------------- stage 4: 3-tap pool + layout ----------------
__global__ void pool_kernel(float* __restrict__ out) {
    int gid = blockIdx.x * 256 + threadIdx.x;   // < 32768 = B*L*H
    int b = gid / (Ll * Hh);
    int r = gid % (Ll * Hh);
    int mm = r / Hh;
    int h = r % Hh;
    int base = (h * Bb + b) * Ll;
    float sm = Spart[0][base + mm] + Spart[1][base + mm];
    float sl = (mm > 0)      ? Spart[0][base + mm - 1] + Spart[1][base + mm - 1] : 0.f;
    float sr = (mm < Ll - 1) ? Spart[0][base + mm + 1] + Spart[1][base + mm + 1] : 0.f;
    float inv = (mm == 0 || mm == Ll - 1) ? 0.5f : (1.f / 3.f);
    out[gid] = (sl + sm + sr) * inv;
}

extern "C" void kernel_launch(void* const* d_in, const int* in_sizes, int n_in,
                              void* d_out, int out_size) {
    const float* x  = (const float*)d_in[0];
    const float* pe = (const float*)d_in[1];
    const float* Wq = (const float*)d_in[2];
    const float* bq = (const float*)d_in[3];
    const float* Wk = (const float*)d_in[4];
    const float* bk = (const float*)d_in[5];
    const float* Wv = (const float*)d_in[6];

    proj_kernel<<<256, 256>>>(x, pe, Wq, bq, Wk, bk, Wv);
    denom_kernel<<<512, 128>>>();
    attn_kernel<<<512, 128>>>();
    pool_kernel<<<128, 256>>>((float*)d_out);
}

// round 8
// speedup vs baseline: 1.0030x; 1.0030x over previous
#include <cuda_runtime.h>

#define Bb 2
#define Ll 2048
#define Dd 128
#define Hh 8
#define HDd 32
#define HB (Hh*Bb)   // 16
#define SCALE 0.17677669529663687f
#define QT 64

// ---------------- device scratch (no allocs allowed) ----------------
__device__ float4 Qd4[HB * Ll * 8];        // [h*B+b][l][d] as float4 x8, 4MB
__device__ float4 Kd4[HB * Ll * 8];        // 4MB
__device__ float  Vg[HB * Ll];             // sigmoid(x@Wv), [h*B+b][l]
__device__ float  denomP[2][HB * Ll];      // softmax denominators, 2-way key split
__device__ float  Spart[2][HB * Ll];       // distance histogram, 2-way q split

// ---------------- stage 1: projections ----------------
// 256 blocks x 256 threads; each block handles 16 (b,l) rows, thread t = output col.
__global__ void proj_kernel(const float* __restrict__ x, const float* __restrict__ pe,
                            const float* __restrict__ Wq, const float* __restrict__ bq,
                            const float* __restrict__ Wk, const float* __restrict__ bk,
                            const float* __restrict__ Wv) {
    const int ROWS = 16;
    __shared__ float xs[ROWS][Dd];   // raw x (for v)
    __shared__ float xps[ROWS][Dd];  // x + pe (for q,k)
    int t = threadIdx.x;             // 0..255
    int row0 = blockIdx.x * ROWS;    // global row = b*L + l (16 rows share b: L%16==0)
    int b = row0 / Ll;
    int l0 = row0 % Ll;

    for (int i = t; i < ROWS * Dd; i += 256) {
        int r = i >> 7, dd = i & 127;
        float xv = x[(row0 + r) * Dd + dd];
        xs[r][dd]  = xv;
        xps[r][dd] = xv + pe[(l0 + r) * Dd + dd];
    }
    __syncthreads();

    float accq[ROWS], acck[ROWS], accv[ROWS];
    float bqv = bq[t], bkv = bk[t];
    #pragma unroll
    for (int r = 0; r < ROWS; r++) { accq[r] = bqv; acck[r] = bkv; accv[r] = 0.f; }

    for (int dd = 0; dd < Dd; dd++) {
        float wq = Wq[dd * 256 + t];
        float wk = Wk[dd * 256 + t];
        float wv = (t < Hh) ? Wv[dd * Hh + t] : 0.f;
        #pragma unroll
        for (int r = 0; r < ROWS; r++) {
            float xpv = xps[r][dd];
            accq[r] += xpv * wq;
            acck[r] += xpv * wk;
            accv[r] += xs[r][dd] * wv;  // only meaningful for t < 8
        }
    }

    int h = t >> 5, d = t & 31;
    float* Qs = (float*)Qd4;
    float* Ks = (float*)Kd4;
    #pragma unroll
    for (int r = 0; r < ROWS; r++) {
        int l = l0 + r;
        Qs[((h * Bb + b) * Ll + l) * 32 + d] = accq[r];
        Ks[((h * Bb + b) * Ll + l) * 32 + d] = acck[r];
        if (t < Hh)
            Vg[(t * Bb + b) * Ll + l] = 1.f / (1.f + __expf(-accv[r]));
    }
}

// ---------------- stage 2: softmax denominators ----------------
// 512 blocks x 128 threads. block = (hb, qchunk of 128, ks half of key tiles)
__global__ void denom_kernel() {
    __shared__ float4 ks4[128][8];
    int t = threadIdx.x;
    int bx = blockIdx.x;
    int hb = bx >> 5;
    int rem = bx & 31;
    int qc = rem >> 1;
    int ks = rem & 1;
    int q = qc * 128 + t;

    float4 qv[8];
    #pragma unroll
    for (int d4 = 0; d4 < 8; d4++) qv[d4] = Qd4[(hb * Ll + q) * 8 + d4];

    float acc = 0.f;
    for (int kt = ks; kt < 16; kt += 2) {
        #pragma unroll
        for (int d4 = 0; d4 < 8; d4++)
            ks4[t][d4] = Kd4[(hb * Ll + kt * 128 + t) * 8 + d4];
        __syncthreads();
        #pragma unroll 4
        for (int j = 0; j < 128; j++) {
            float s0 = 0.f, s1 = 0.f, s2 = 0.f, s3 = 0.f;
            #pragma unroll
            for (int d4 = 0; d4 < 8; d4++) {
                float4 kk = ks4[j][d4];
                float4 qq = qv[d4];
                s0 += qq.x * kk.x; s1 += qq.y * kk.y;
                s2 += qq.z * kk.z; s3 += qq.w * kk.w;
            }
            acc += __expf(((s0 + s1) + (s2 + s3)) * SCALE);
        }
        __syncthreads();
    }
    denomP[ks][hb * Ll + q] = acc;
}

// ---------------- stage 3: diagonal accumulation ----------------
// 512 blocks x 128 threads. block = (hb, mchunk of 128, qs half of q tiles).
// thread owns distance m = mchunk*128 + t; accumulates S[m] in a register.
__global__ void attn_kernel() {
    __shared__ float4 qs4[QT][8];      // q tile, broadcast reads
    __shared__ float  kT[32][193];     // k tile transposed, padded: conflict-free
    __shared__ float  dinv[QT];        // 1/denom per query
    __shared__ float  vvs[192];        // v gate per key row
    int t = threadIdx.x;
    int bx = blockIdx.x;
    int hb = bx >> 5;
    int rem = bx & 31;
    int mc = rem >> 1;
    int qs = rem & 1;
    int m0 = mc * 128;
    int m = m0 + t;

    float acc = 0.f;
    for (int q0 = qs * QT; q0 < Ll - m0; q0 += 2 * QT) {
        int kbase = q0 + m0;
        // q tile: 64 rows x 8 float4
        for (int i = t; i < QT * 8; i += 128) {
            int ri = i >> 3, d4 = i & 7;
            int row = q0 + ri;
            qs4[ri][d4] = (row < Ll) ? Qd4[(hb * Ll + row) * 8 + d4]
                                     : make_float4(0.f, 0.f, 0.f, 0.f);
        }
        // k tile transposed: 192 rows x 32 dims -> kT[d][row]
        for (int i = t; i < 192 * 8; i += 128) {
            int ri = i >> 3, d4 = i & 7;
            int row = kbase + ri;
            float4 kv = (row < Ll) ? Kd4[(hb * Ll + row) * 8 + d4]
                                   : make_float4(0.f, 0.f, 0.f, 0.f);
            kT[d4 * 4 + 0][ri] = kv.x;
            kT[d4 * 4 + 1][ri] = kv.y;
            kT[d4 * 4 + 2][ri] = kv.z;
            kT[d4 * 4 + 3][ri] = kv.w;
        }
        if (t < QT) {
            int row = q0 + t;
            dinv[t] = (row < Ll)
                ? __fdividef(1.f, denomP[0][hb * Ll + row] + denomP[1][hb * Ll + row])
                : 0.f;
        }
        for (int i = t; i < 192; i += 128) {
            int kk = kbase + i;
            vvs[i] = (kk < Ll) ? Vg[hb * Ll + (Ll - 1 - kk)] : 0.f;
        }
        __syncthreads();

        int n = Ll - m - q0;             // valid iff q0+qi+m < L
        if (n > QT) n = QT;
        for (int qi = 0; qi < n; qi++) {
            int r = qi + t;              // <= 63+127 = 190 < 192
            float s0 = 0.f, s1 = 0.f, s2 = 0.f, s3 = 0.f;
            #pragma unroll
            for (int d4 = 0; d4 < 8; d4++) {
                float4 qq = qs4[qi][d4];
                s0 += qq.x * kT[d4 * 4 + 0][r];
                s1 += qq.y * kT[d4 * 4 + 1][r];
                s2 += qq.z * kT[d4 * 4 + 2][r];
                s3 += qq.w * kT[d4 * 4 + 3][r];
            }
            acc += __expf(((s0 + s1) + (s2 + s3)) * SCALE) * dinv[qi] * vvs[r];
        }
        __syncthreads();
    }
    Spart[qs][hb * Ll + m] = acc;
}

// ---------------- stage 4: 3-tap pool + layout ----------------
__global__ void pool_kernel(float* __restrict__ out) {
    int gid = blockIdx.x * 256 + threadIdx.x;   // < 32768 = B*L*H
    int b = gid / (Ll * Hh);
    int r = gid % (Ll * Hh);
    int mm = r / Hh;
    int h = r % Hh;
    int base = (h * Bb + b) * Ll;
    float sm = Spart[0][base + mm] + Spart[1][base + mm];
    float sl = (mm > 0)      ? Spart[0][base + mm - 1] + Spart[1][base + mm - 1] : 0.f;
    float sr = (mm < Ll - 1) ? Spart[0][base + mm + 1] + Spart[1][base + mm + 1] : 0.f;
    float inv = (mm == 0 || mm == Ll - 1) ? 0.5f : (1.f / 3.f);
    out[gid] = (sl + sm + sr) * inv;
}

extern "C" void kernel_launch(void* const* d_in, const int* in_sizes, int n_in,
                              void* d_out, int out_size) {
    const float* x  = (const float*)d_in[0];
    const float* pe = (const float*)d_in[1];
    const float* Wq = (const float*)d_in[2];
    const float* bq = (const float*)d_in[3];
    const float* Wk = (const float*)d_in[4];
    const float* bk = (const float*)d_in[5];
    const float* Wv = (const float*)d_in[6];

    proj_kernel<<<256, 256>>>(x, pe, Wq, bq, Wk, bk, Wv);
    denom_kernel<<<512, 128>>>();
    attn_kernel<<<512, 128>>>();
    pool_kernel<<<128, 256>>>((float*)d_out);
}